// round 5
// baseline (speedup 1.0000x reference)
#include <cuda_runtime.h>

// ---------------------------------------------------------------------------
// RLFrameSelector: B=32, T=2048, F=512, U=128, k=64
// Score pass: packed-fp32 (FFMA2) GEMM — measured fastest engine on this
// bench (tcgen05 blocked by compute_100 target; legacy HMMA ~66 TF/s < FFMA2).
// ---------------------------------------------------------------------------

#define B_   32
#define T_   2048
#define F_   512
#define U_   128
#define NFRAMES (B_ * T_)        // 65536
#define NEG_BIG_F (-1.0e9f)

typedef unsigned long long u64;

static __device__ float         g_scores[NFRAMES];
static __device__ unsigned char g_sel[NFRAMES];

// ---- packed f32x2 helpers (ptxas never auto-emits these from C++) ---------
__device__ __forceinline__ u64 pack2(float lo, float hi) {
    u64 r;
    asm("mov.b64 %0, {%1, %2};" : "=l"(r) : "f"(lo), "f"(hi));
    return r;
}
__device__ __forceinline__ void unpack2(u64 v, float& lo, float& hi) {
    asm("mov.b64 {%0, %1}, %2;" : "=f"(lo), "=f"(hi) : "l"(v));
}
__device__ __forceinline__ void ffma2(u64& d, u64 a, u64 b) {
    asm("fma.rn.f32x2 %0, %1, %2, %0;" : "+l"(d) : "l"(a), "l"(b));
}
__device__ __forceinline__ void fadd2(u64& d, u64 a) {
    asm("add.rn.f32x2 %0, %1, %2;" : "=l"(d) : "l"(d), "l"(a));
}

// ---------------------------------------------------------------------------
// Pass 1: fused scoring GEMM. Block tile 128 frames x 128 u, K staged by 16,
// double-buffered. 256 threads: u_tid=tid&15 owns u=u_tid*8..+7, fr_tid=tid>>4
// owns frames fr_tid*8..+7 (4 f32x2 pairs). Per k: 6 LDS.128 -> 32 FFMA2.
// W smem is pre-DUPLICATED ([w,w] pairs) so no pack movs in the hot loop.
// ---------------------------------------------------------------------------
#define KB    16
#define NST   (F_ / KB)          // 32
#define XSTR  132                // padded x row stride (floats), 16B-aligned rows
#define WSTR  256                // duplicated w row stride (floats)
#define XS_OFF 0
#define WS_OFF (2 * KB * XSTR)               // 4224 floats
#define NZ_OFF (WS_OFF + 2 * KB * WSTR)      // 12416 floats
#define SMEM_BYTES ((NZ_OFF + 128) * 4)      // 50176 B

extern __shared__ float S[];

__global__ __launch_bounds__(256, 2) void score_kernel(
    const float* __restrict__ x, const float* __restrict__ W1,
    const float* __restrict__ b1, const float* __restrict__ W2,
    const float* __restrict__ b2)
{
    float* xs = S + XS_OFF;
    float* ws = S + WS_OFF;
    int*   nz = (int*)(S + NZ_OFF);

    const int tid    = threadIdx.x;
    const int u_tid  = tid & 15;
    const int fr_tid = tid >> 4;
    const long frame0 = (long)blockIdx.x * 128;

    if (tid < 128) nz[tid] = 0;

    // x stager: frame sf (two threads/frame), 8 consecutive k each
    const int sf = tid >> 1, sh = tid & 1;
    const float* xg = x + (frame0 + sf) * F_ + sh * 8;
    // w stager: k-row sk, 8 consecutive u each (stored duplicated)
    const int sk = tid >> 4, suq = tid & 15;
    const float* wg = W1 + sk * U_ + suq * 8;

    u64 acc[8][4];
#pragma unroll
    for (int a = 0; a < 8; a++)
#pragma unroll
        for (int p = 0; p < 4; p++) acc[a][p] = 0ull;

    int nzf = 0;
    float4 xr0, xr1, wr0, wr1;

    // ---- prologue: stage 0 into buffer 0
    xr0 = *(const float4*)(xg);
    xr1 = *(const float4*)(xg + 4);
    wr0 = *(const float4*)(wg);
    wr1 = *(const float4*)(wg + 4);
    {
        float vx[8] = {xr0.x, xr0.y, xr0.z, xr0.w, xr1.x, xr1.y, xr1.z, xr1.w};
#pragma unroll
        for (int j = 0; j < 8; j++) {
            xs[(sh * 8 + j) * XSTR + sf] = vx[j];
            if (vx[j] != 0.f) nzf = 1;
        }
        float* wp = &ws[sk * WSTR + suq * 16];
        ((float4*)wp)[0] = make_float4(wr0.x, wr0.x, wr0.y, wr0.y);
        ((float4*)wp)[1] = make_float4(wr0.z, wr0.z, wr0.w, wr0.w);
        ((float4*)wp)[2] = make_float4(wr1.x, wr1.x, wr1.y, wr1.y);
        ((float4*)wp)[3] = make_float4(wr1.z, wr1.z, wr1.w, wr1.w);
    }
    __syncthreads();

#pragma unroll 1
    for (int s = 0; s < NST; s++) {
        const int buf = s & 1;
        const bool have = (s + 1 < NST);
        if (have) {
            xr0 = *(const float4*)(xg + (s + 1) * KB);
            xr1 = *(const float4*)(xg + (s + 1) * KB + 4);
            wr0 = *(const float4*)(wg + (s + 1) * KB * U_);
            wr1 = *(const float4*)(wg + (s + 1) * KB * U_ + 4);
        }
        const float* xb = &xs[(buf * KB) * XSTR + fr_tid * 8];
        const float* wb = &ws[(buf * KB) * WSTR + u_tid * 16];
#pragma unroll
        for (int k = 0; k < KB; k++) {
            const ulonglong2 xA = *(const ulonglong2*)(xb + k * XSTR);
            const ulonglong2 xB = *(const ulonglong2*)(xb + k * XSTR + 4);
            const u64 xp0 = xA.x, xp1 = xA.y, xp2 = xB.x, xp3 = xB.y;
            const ulonglong2 wA = *(const ulonglong2*)(wb + k * WSTR);
            const ulonglong2 wB = *(const ulonglong2*)(wb + k * WSTR + 4);
            const ulonglong2 wC = *(const ulonglong2*)(wb + k * WSTR + 8);
            const ulonglong2 wD = *(const ulonglong2*)(wb + k * WSTR + 12);
            const u64 wp[8] = {wA.x, wA.y, wB.x, wB.y, wC.x, wC.y, wD.x, wD.y};
#pragma unroll
            for (int a = 0; a < 8; a++) {
                ffma2(acc[a][0], xp0, wp[a]);
                ffma2(acc[a][1], xp1, wp[a]);
                ffma2(acc[a][2], xp2, wp[a]);
                ffma2(acc[a][3], xp3, wp[a]);
            }
        }
        if (have) {
            const int nb = buf ^ 1;
            float vx[8] = {xr0.x, xr0.y, xr0.z, xr0.w, xr1.x, xr1.y, xr1.z, xr1.w};
#pragma unroll
            for (int j = 0; j < 8; j++) {
                xs[(nb * KB + sh * 8 + j) * XSTR + sf] = vx[j];
                if (vx[j] != 0.f) nzf = 1;
            }
            float* wp = &ws[(nb * KB + sk) * WSTR + suq * 16];
            ((float4*)wp)[0] = make_float4(wr0.x, wr0.x, wr0.y, wr0.y);
            ((float4*)wp)[1] = make_float4(wr0.z, wr0.z, wr0.w, wr0.w);
            ((float4*)wp)[2] = make_float4(wr1.x, wr1.x, wr1.y, wr1.y);
            ((float4*)wp)[3] = make_float4(wr1.z, wr1.z, wr1.w, wr1.w);
        }
        __syncthreads();
    }

    // ---- epilogue: +b1, relu, *W2, reduce over 16 u-threads (width-16 shfl)
    if (nzf) nz[sf] = 1;      // two stagers per frame, same value: benign
    __syncthreads();

    float4 b1a = *(const float4*)(b1 + u_tid * 8);
    float4 b1b = *(const float4*)(b1 + u_tid * 8 + 4);
    float4 w2a = *(const float4*)(W2 + u_tid * 8);
    float4 w2b = *(const float4*)(W2 + u_tid * 8 + 4);
    const float beta = b2[0];
    const float bv[8] = {b1a.x, b1a.y, b1a.z, b1a.w, b1b.x, b1b.y, b1b.z, b1b.w};
    const float wv[8] = {w2a.x, w2a.y, w2a.z, w2a.w, w2b.x, w2b.y, w2b.z, w2b.w};

    u64 part[4] = {0ull, 0ull, 0ull, 0ull};
#pragma unroll
    for (int a = 0; a < 8; a++) {
        const u64 bp = pack2(bv[a], bv[a]);
        const u64 wp = pack2(wv[a], wv[a]);
#pragma unroll
        for (int p = 0; p < 4; p++) {
            u64 h = acc[a][p];
            fadd2(h, bp);
            float lo, hi; unpack2(h, lo, hi);
            ffma2(part[p], pack2(fmaxf(lo, 0.f), fmaxf(hi, 0.f)), wp);
        }
    }
#pragma unroll
    for (int off = 8; off > 0; off >>= 1)
#pragma unroll
        for (int p = 0; p < 4; p++) {
            u64 o = __shfl_down_sync(0xffffffffu, part[p], off, 16);
            fadd2(part[p], o);
        }
    if (u_tid == 0) {
#pragma unroll
        for (int p = 0; p < 4; p++) {
            float lo, hi; unpack2(part[p], lo, hi);
            const int f = fr_tid * 8 + 2 * p;
            g_scores[frame0 + f]     = nz[f]     ? (lo + beta) : NEG_BIG_F;
            g_scores[frame0 + f + 1] = nz[f + 1] ? (hi + beta) : NEG_BIG_F;
        }
    }
}

// ---------------------------------------------------------------------------
// Pass 2: top-64 per row, register-resident keys, 1 barrier/iteration.
// Key = (monotone-mapped score, 2047-idx): stable lowest-index tie-break.
// Winner clears its OWN register & sets its OWN g_sel byte (no races).
// ---------------------------------------------------------------------------
__global__ __launch_bounds__(256) void topk_kernel()
{
    __shared__ u64 red[16];    // double-buffered 8-warp reduce slots
    const int row  = blockIdx.x;
    const int tid  = threadIdx.x;
    const int lane = tid & 31;
    const int wid  = tid >> 5;
    const float* sc = g_scores + row * T_;

    u64 key[8];
#pragma unroll
    for (int j = 0; j < 8; j++) {
        const int i = tid + j * 256;
        unsigned u = __float_as_uint(sc[i]);
        u = (u & 0x80000000u) ? ~u : (u | 0x80000000u);
        key[j] = ((u64)u << 32) | (unsigned)(T_ - 1 - i);
        g_sel[row * T_ + i] = 0;      // own element; set later by same thread
    }

    for (int it = 0; it < 64; it++) {
        u64 best = key[0];
#pragma unroll
        for (int j = 1; j < 8; j++) if (key[j] > best) best = key[j];
#pragma unroll
        for (int off = 16; off > 0; off >>= 1) {
            u64 o = __shfl_down_sync(0xffffffffu, best, off);
            if (o > best) best = o;
        }
        if (lane == 0) red[(it & 1) * 8 + wid] = best;
        __syncthreads();
        u64 v = (lane < 8) ? red[(it & 1) * 8 + lane] : 0ull;
#pragma unroll
        for (int off = 4; off > 0; off >>= 1) {
            u64 o = __shfl_down_sync(0xffffffffu, v, off);
            if (o > v) v = o;
        }
        const u64 win = __shfl_sync(0xffffffffu, v, 0);
        const int i = (T_ - 1) - (int)(unsigned)(win & 0xffffffffu);
        if ((i & 255) == tid) {
            const int jj = i >> 8;
#pragma unroll
            for (int j = 0; j < 8; j++) if (j == jj) key[j] = 0ull;
            g_sel[row * T_ + i] = 1;
        }
    }
}

// ---------------------------------------------------------------------------
// Pass 3: out = sel ? x : 0; 2 float4 per thread.
// ---------------------------------------------------------------------------
__global__ __launch_bounds__(256) void output_kernel(
    const float4* __restrict__ x4, float4* __restrict__ out4)
{
    const long g0 = ((long)blockIdx.x * 256 + threadIdx.x) * 2;
#pragma unroll
    for (int e = 0; e < 2; e++) {
        const long gid = g0 + e;
        const int frame = (int)(gid >> 7);       // 128 float4 per frame
        float4 v = make_float4(0.f, 0.f, 0.f, 0.f);
        if (g_sel[frame]) v = x4[gid];
        out4[gid] = v;
    }
}

// ---------------------------------------------------------------------------
extern "C" void kernel_launch(void* const* d_in, const int* in_sizes, int n_in,
                              void* d_out, int out_size)
{
    (void)in_sizes; (void)n_in;
    const float* x  = (const float*)d_in[0];
    const float* W1 = (const float*)d_in[1];
    const float* b1 = (const float*)d_in[2];
    const float* W2 = (const float*)d_in[3];
    const float* b2 = (const float*)d_in[4];
    // d_in[5] is k (fixed at 64 by problem spec)

    cudaFuncSetAttribute(score_kernel,
                         cudaFuncAttributeMaxDynamicSharedMemorySize, SMEM_BYTES);

    score_kernel<<<NFRAMES / 128, 256, SMEM_BYTES>>>(x, W1, b1, W2, b2);
    topk_kernel<<<B_, 256>>>();
    const int n4 = out_size / 4;                 // 8388608 float4
    output_kernel<<<n4 / 512, 256>>>((const float4*)x, (float4*)d_out);
}